// round 11
// baseline (speedup 1.0000x reference)
#include <cuda_runtime.h>
#include <math.h>

// Problem constants (fixed by reference setup_inputs)
#define BB    512
#define KK    8
#define PP    6
#define DD    1024
#define NIDS  64
#define MARGIN 0.2f
#define GRID  (BB * PP)           // 3072 blocks

// Cross-call accumulator state (statically zero-initialized; reset by the
// last-done block each call, so graph replays are deterministic).
__device__ float        g_accum = 0.0f;
__device__ unsigned int g_done  = 0u;

// ---------------------------------------------------------------------------
// Fused kernel: one block per (b,p).
//   Phase A (cheap): scan pids/camids for pid==pid_b only -> own_cnt,
//     cross_cnt, cross member list. No histogram (denominator factored out).
//   Phase B: stage own f_original row + gathered cross-center row in SMEM.
//   Phase C (R4 shape): warp k streams f_generated[b,k,p,:], 8 batched
//     float4 loads vs SMEM rows; hinge; block partial.
//   Phase D: accumulate un-normalized sum; last-done block builds the
//     one-off 128-bin histogram, computes id_count, normalizes, writes out.
// ---------------------------------------------------------------------------
__global__ void __launch_bounds__(256) cpm_fused(const float* __restrict__ f_orig,
                                                 const float* __restrict__ f_gen,
                                                 const int*   __restrict__ pids,
                                                 const int*   __restrict__ camids,
                                                 float*       __restrict__ out) {
    __shared__ float so[DD];              // own f_original row      (4 KB)
    __shared__ float sc[DD];              // cross-center row        (4 KB)
    __shared__ int   slist[BB];           // cross-group members     (2 KB)
    __shared__ int   snm;                 // cross count
    __shared__ int   sown;                // own-modality count (incl. b)
    __shared__ float spart[8];
    __shared__ int   is_last;
    __shared__ int   scnt[2 * NIDS];      // last-block histogram
    __shared__ int   sidc;

    int bp = blockIdx.x;                  // 0 .. GRID-1
    int b = bp / PP;
    int p = bp - b * PP;
    int t = threadIdx.x;                  // 256 threads
    int w = t >> 5;
    int lane = t & 31;

    // ---- Phase A: match-only scan ---------------------------------------
    if (t == 0) { snm = 0; sown = 0; }
    __syncthreads();

    int pid_b = pids[b];
    int cross_mod = (camids[b] == 0) ? 1 : 0;

#pragma unroll
    for (int i = t; i < BB; i += 256) {
        int pid = pids[i];
        if (pid == pid_b) {
            int mod = (camids[i] == 0) ? 0 : 1;
            if (mod == cross_mod) {
                int pos = atomicAdd(&snm, 1);
                slist[pos] = i;
            } else {
                atomicAdd(&sown, 1);
            }
        }
    }
    __syncthreads();

    int cnt = snm;                         // cross-modality count
    // weight without global denominator; valid iff cross group non-empty
    float wgt = (cnt > 0)
        ? (1.0f / ((float)sown * (float)KK * (float)PP)) : 0.0f;
    float cinv = 1.0f / fmaxf((float)cnt, 1.0f);

    // ---- Phase B: prologue ----------------------------------------------
    const float4* fo4 = reinterpret_cast<const float4*>(f_orig);
    float4* so4 = reinterpret_cast<float4*>(so);
    float4* sc4 = reinterpret_cast<float4*>(sc);

    so4[t] = fo4[(((size_t)(b * PP + p) * DD) >> 2) + t];

    float4 acc = make_float4(0.f, 0.f, 0.f, 0.f);
    int j = 0;
    for (; j + 4 <= cnt; j += 4) {
        int b0 = slist[j + 0], b1 = slist[j + 1];
        int b2 = slist[j + 2], b3 = slist[j + 3];
        float4 v0 = fo4[(((size_t)(b0 * PP + p) * DD) >> 2) + t];
        float4 v1 = fo4[(((size_t)(b1 * PP + p) * DD) >> 2) + t];
        float4 v2 = fo4[(((size_t)(b2 * PP + p) * DD) >> 2) + t];
        float4 v3 = fo4[(((size_t)(b3 * PP + p) * DD) >> 2) + t];
        acc.x += (v0.x + v1.x) + (v2.x + v3.x);
        acc.y += (v0.y + v1.y) + (v2.y + v3.y);
        acc.z += (v0.z + v1.z) + (v2.z + v3.z);
        acc.w += (v0.w + v1.w) + (v2.w + v3.w);
    }
    for (; j < cnt; ++j) {
        int bs = slist[j];
        float4 v = fo4[(((size_t)(bs * PP + p) * DD) >> 2) + t];
        acc.x += v.x; acc.y += v.y; acc.z += v.z; acc.w += v.w;
    }
    acc.x *= cinv; acc.y *= cinv; acc.z *= cinv; acc.w *= cinv;
    sc4[t] = acc;
    __syncthreads();

    // ---- Phase C: main stream (R4 shape) --------------------------------
    const float4* gp = reinterpret_cast<const float4*>(
        f_gen + ((size_t)((b * KK + w) * PP + p)) * DD);

    float4 g[8];
#pragma unroll
    for (int it = 0; it < 8; ++it) g[it] = gp[it * 32 + lane];

    float s_pull = 0.0f, s_push = 0.0f;
#pragma unroll
    for (int it = 0; it < 8; ++it) {
        float4 o = so4[it * 32 + lane];
        float4 c = sc4[it * 32 + lane];
        float dx, dy, dz, dw;
        dx = g[it].x - c.x; dy = g[it].y - c.y;
        dz = g[it].z - c.z; dw = g[it].w - c.w;
        s_pull += dx * dx + dy * dy + dz * dz + dw * dw;
        dx = g[it].x - o.x; dy = g[it].y - o.y;
        dz = g[it].z - o.z; dw = g[it].w - o.w;
        s_push += dx * dx + dy * dy + dz * dz + dw * dw;
    }
#pragma unroll
    for (int s = 16; s; s >>= 1) {
        s_pull += __shfl_down_sync(0xffffffffu, s_pull, s);
        s_push += __shfl_down_sync(0xffffffffu, s_push, s);
    }
    if (lane == 0) {
        float h = sqrtf(s_pull) - sqrtf(s_push) + MARGIN;
        spart[w] = fmaxf(h, 0.0f);
    }
    __syncthreads();

    // ---- Phase D: epilogue ----------------------------------------------
    if (t == 0) {
        float s = 0.0f;
#pragma unroll
        for (int i = 0; i < 8; ++i) s += spart[i];
        atomicAdd(&g_accum, s * wgt);
        __threadfence();
        unsigned r = atomicAdd(&g_done, 1u);
        is_last = (r == (unsigned)(GRID - 1)) ? 1 : 0;
    }
    __syncthreads();

    if (is_last) {
        // One-off global setup: id_count via 128-bin histogram.
        if (t < 2 * NIDS) scnt[t] = 0;
        if (t == 0) sidc = 0;
        __syncthreads();
#pragma unroll
        for (int i = t; i < BB; i += 256) {
            int pid = pids[i];
            int mod = (camids[i] == 0) ? 0 : 1;
            atomicAdd(&scnt[mod * NIDS + pid], 1);
        }
        __syncthreads();
        if (t < NIDS) {
            if (scnt[t] > 0 && scnt[NIDS + t] > 0) atomicAdd(&sidc, 1);
        }
        __syncthreads();
        if (t == 0) {
            float denom = fmaxf((float)sidc, 1.0f);
            float v = atomicExch(&g_accum, 0.0f);   // read + reset for replay
            out[0] = v / denom;
            g_done = 0u;
        }
    }
}

// ---------------------------------------------------------------------------
extern "C" void kernel_launch(void* const* d_in, const int* in_sizes, int n_in,
                              void* d_out, int out_size) {
    const float* f_orig = (const float*)d_in[0];
    const float* f_gen  = (const float*)d_in[1];
    const int*   pids   = (const int*)d_in[2];
    const int*   camids = (const int*)d_in[3];
    float*       out    = (float*)d_out;

    cpm_fused<<<GRID, 256>>>(f_orig, f_gen, pids, camids, out);
}

// round 12
// speedup vs baseline: 1.0759x; 1.0759x over previous
#include <cuda_runtime.h>
#include <math.h>

// Problem constants (fixed by reference setup_inputs)
#define BB    512
#define KK    8
#define PP    6
#define DD    1024
#define NIDS  64
#define NGRP  (2 * NIDS)
#define MARGIN 0.2f
#define GRID  (BB * PP)           // 3072 blocks

// Scratch (no allocations allowed)
__device__ float g_w[BB];         // fused per-sample weight (1/(grp*K*P*denom))
__device__ float g_cinv[BB];      // 1/max(cnt_cross,1)
__device__ int   g_boff[BB];      // CSR offset of sample b's CROSS group
__device__ int   g_bcnt[BB];      // count of sample b's CROSS group
__device__ int   g_list[BB];      // CSR sample indices grouped by (mod,id)

// ---------------------------------------------------------------------------
// K1: one block, 512 threads. Histogram, validity, id_count, parallel
//     exclusive scan (shfl), fused weights, CSR lists, zero d_out.
// ---------------------------------------------------------------------------
__global__ void k1_setup(const int* __restrict__ pids,
                         const int* __restrict__ camids,
                         float* __restrict__ out) {
    __shared__ int scnt[NGRP];
    __shared__ int scur[NGRP];
    __shared__ int soff[NGRP];        // exclusive prefix of scnt
    __shared__ int svalid[NIDS];
    __shared__ int s_idcount;
    __shared__ int warpsum[4];

    int t = threadIdx.x;
    if (t < NGRP) { scnt[t] = 0; scur[t] = 0; }
    if (t == 0) s_idcount = 0;
    __syncthreads();

    int pid = 0, cam = 0, own_grp = 0;
    if (t < BB) {
        pid = pids[t];
        cam = camids[t];
        int mod = (cam == 0) ? 0 : 1;
        own_grp = mod * NIDS + pid;
        atomicAdd(&scnt[own_grp], 1);
    }
    __syncthreads();

    if (t < NIDS) {
        int v = (scnt[t] > 0 && scnt[NIDS + t] > 0) ? 1 : 0;
        svalid[t] = v;
        if (v) atomicAdd(&s_idcount, 1);
    }

    // Parallel exclusive scan of scnt[0..127] using first 4 warps
    int v = 0, inc = 0;
    if (t < NGRP) {
        v = scnt[t];
        inc = v;
        int lane = t & 31;
#pragma unroll
        for (int d = 1; d < 32; d <<= 1) {
            int n = __shfl_up_sync(0xffffffffu, inc, d);
            if (lane >= d) inc += n;
        }
        if (lane == 31) warpsum[t >> 5] = inc;
    }
    __syncthreads();
    if (t == 0) {
        int a = 0;
#pragma unroll
        for (int i = 0; i < 4; ++i) { int x = warpsum[i]; warpsum[i] = a; a += x; }
    }
    __syncthreads();
    if (t < NGRP) soff[t] = inc - v + warpsum[t >> 5];   // exclusive prefix
    __syncthreads();

    float denom = fmaxf((float)s_idcount, 1.0f);

    if (t < BB) {
        int rgb = (cam == 0);
        int cross_grp = (rgb ? 1 : 0) * NIDS + pid;
        float grp_cnt = fmaxf((float)scnt[own_grp], 1.0f);
        float w = svalid[pid] ? (1.0f / (grp_cnt * (float)KK * (float)PP * denom)) : 0.0f;
        g_w[t] = w;
        g_cinv[t] = 1.0f / fmaxf((float)scnt[cross_grp], 1.0f);
        g_boff[t] = soff[cross_grp];
        g_bcnt[t] = scnt[cross_grp];
        int pos = atomicAdd(&scur[own_grp], 1);
        g_list[soff[own_grp] + pos] = t;
    }
    if (t == 0) out[0] = 0.0f;
}

// ---------------------------------------------------------------------------
// K4 (R4 shape + PDL): one block per (b,p). Stage own row (independent of
//     k1), griddepcontrol.wait, gather cross-center via CSR, then 8 warps
//     each stream one k-row of f_gen with 8 batched float4 loads.
// ---------------------------------------------------------------------------
__global__ void __launch_bounds__(256) k4_main(const float* __restrict__ f_orig,
                                               const float* __restrict__ f_gen,
                                               float* __restrict__ out) {
    __shared__ float so[DD];          // own f_original row
    __shared__ float sc[DD];          // cross-modality center row
    __shared__ float spart[8];

    int bp = blockIdx.x;              // 0 .. GRID-1
    int b = bp / PP;
    int p = bp - b * PP;
    int t = threadIdx.x;              // 256 threads; thread t owns float4 #t
    int w = t >> 5;
    int lane = t & 31;

    const float4* fo4 = reinterpret_cast<const float4*>(f_orig);
    float4* so4 = reinterpret_cast<float4*>(so);
    float4* sc4 = reinterpret_cast<float4*>(sc);

    // Stage own row — independent of k1, overlaps with k1 completion
    so4[t] = fo4[(((size_t)(b * PP + p) * DD) >> 2) + t];

    // Wait for k1's outputs to be visible (PDL sync point)
    asm volatile("griddepcontrol.wait;" ::: "memory");

    // Gather cross-center row over CSR member list
    int off = g_boff[b];
    int cnt = g_bcnt[b];
    float cinv = g_cinv[b];
    float4 acc = make_float4(0.f, 0.f, 0.f, 0.f);
    int j = 0;
    for (; j + 4 <= cnt; j += 4) {
        int b0 = g_list[off + j + 0], b1 = g_list[off + j + 1];
        int b2 = g_list[off + j + 2], b3 = g_list[off + j + 3];
        float4 v0 = fo4[(((size_t)(b0 * PP + p) * DD) >> 2) + t];
        float4 v1 = fo4[(((size_t)(b1 * PP + p) * DD) >> 2) + t];
        float4 v2 = fo4[(((size_t)(b2 * PP + p) * DD) >> 2) + t];
        float4 v3 = fo4[(((size_t)(b3 * PP + p) * DD) >> 2) + t];
        acc.x += (v0.x + v1.x) + (v2.x + v3.x);
        acc.y += (v0.y + v1.y) + (v2.y + v3.y);
        acc.z += (v0.z + v1.z) + (v2.z + v3.z);
        acc.w += (v0.w + v1.w) + (v2.w + v3.w);
    }
    for (; j < cnt; ++j) {
        int bs = g_list[off + j];
        float4 vv = fo4[(((size_t)(bs * PP + p) * DD) >> 2) + t];
        acc.x += vv.x; acc.y += vv.y; acc.z += vv.z; acc.w += vv.w;
    }
    acc.x *= cinv; acc.y *= cinv; acc.z *= cinv; acc.w *= cinv;
    sc4[t] = acc;
    __syncthreads();

    // Main stream: warp w handles f_generated[b, w, p, :]
    const float4* gp = reinterpret_cast<const float4*>(
        f_gen + ((size_t)((b * KK + w) * PP + p)) * DD);

    float4 g[8];
#pragma unroll
    for (int it = 0; it < 8; ++it) g[it] = gp[it * 32 + lane];

    float s_pull = 0.0f, s_push = 0.0f;
#pragma unroll
    for (int it = 0; it < 8; ++it) {
        float4 o = so4[it * 32 + lane];
        float4 c = sc4[it * 32 + lane];
        float dx, dy, dz, dw;
        dx = g[it].x - c.x; dy = g[it].y - c.y;
        dz = g[it].z - c.z; dw = g[it].w - c.w;
        s_pull += dx * dx + dy * dy + dz * dz + dw * dw;
        dx = g[it].x - o.x; dy = g[it].y - o.y;
        dz = g[it].z - o.z; dw = g[it].w - o.w;
        s_push += dx * dx + dy * dy + dz * dz + dw * dw;
    }
#pragma unroll
    for (int s = 16; s; s >>= 1) {
        s_pull += __shfl_down_sync(0xffffffffu, s_pull, s);
        s_push += __shfl_down_sync(0xffffffffu, s_push, s);
    }
    if (lane == 0) {
        float h = sqrtf(s_pull) - sqrtf(s_push) + MARGIN;
        spart[w] = fmaxf(h, 0.0f);
    }
    __syncthreads();
    if (t == 0) {
        float s = 0.0f;
#pragma unroll
        for (int i = 0; i < 8; ++i) s += spart[i];
        atomicAdd(out, s * g_w[b]);
    }
}

// ---------------------------------------------------------------------------
extern "C" void kernel_launch(void* const* d_in, const int* in_sizes, int n_in,
                              void* d_out, int out_size) {
    const float* f_orig = (const float*)d_in[0];
    const float* f_gen  = (const float*)d_in[1];
    const int*   pids   = (const int*)d_in[2];
    const int*   camids = (const int*)d_in[3];
    float*       out    = (float*)d_out;

    k1_setup<<<1, 512>>>(pids, camids, out);

    // PDL: let k4 launch before k1 completes; k4 syncs via griddepcontrol.wait
    cudaLaunchConfig_t cfg = {};
    cfg.gridDim  = dim3(GRID);
    cfg.blockDim = dim3(256);
    cfg.dynamicSmemBytes = 0;
    cfg.stream = 0;
    cudaLaunchAttribute attrs[1];
    attrs[0].id = cudaLaunchAttributeProgrammaticStreamSerialization;
    attrs[0].val.programmaticStreamSerializationAllowed = 1;
    cfg.attrs = attrs;
    cfg.numAttrs = 1;
    cudaLaunchKernelEx(&cfg, k4_main, f_orig, f_gen, out);
}